// round 11
// baseline (speedup 1.0000x reference)
#include <cuda_runtime.h>
#include <cstdint>

// Shape (from reference setup_inputs): B=64, S=1024, D=512, T=2048.
// S, D, T re-derived from in_sizes/out_size at launch; B fixed.
#define BATCH 64
#define MAX_S 1024
#define MAX_T 4096
#define ROWS  8        // output rows per 128-thread group
#define RPB   16       // rows per chunk (2 groups per 256-thread block)
#define GRID_GATHER 1184   // 148 SMs x 8 CTAs -> single wave, persistent

// Scratch (no allocations allowed).
__device__ int g_idx[BATCH * MAX_T];   // idx[b][t] = source row for output slot t
__device__ int g_len[BATCH];           // total length per batch

// ---------------------------------------------------------------------------
// Kernel 1 (prep): per-batch inclusive scan via warp shuffles, inverse-map
// scatter (source s owns output slots [cum[s]-dur[s], cum[s])), mask write.
// One block per batch, S=1024 threads. Proven R8 body + PDL trigger.
// ---------------------------------------------------------------------------
__global__ void prep_kernel(const int* __restrict__ dur,
                            float* __restrict__ mask, int S, int T) {
    __shared__ int warp_sums[32];
    __shared__ int s_len;
    const int tid = threadIdx.x;
    const int b   = blockIdx.x;
    const int ln  = tid & 31;

    const int d = dur[b * S + tid];

    // intra-warp inclusive scan
    int v = d;
    #pragma unroll
    for (int o = 1; o < 32; o <<= 1) {
        int n = __shfl_up_sync(0xffffffffu, v, o);
        if (ln >= o) v += n;
    }
    if (ln == 31) warp_sums[tid >> 5] = v;
    __syncthreads();

    // scan of the 32 warp totals by warp 0
    if (tid < 32) {
        int w = warp_sums[tid];
        #pragma unroll
        for (int o = 1; o < 32; o <<= 1) {
            int n = __shfl_up_sync(0xffffffffu, w, o);
            if (tid >= o) w += n;
        }
        warp_sums[tid] = w;
        if (tid == 31) s_len = w;
    }
    __syncthreads();

    const int base  = (tid >= 32) ? warp_sums[(tid >> 5) - 1] : 0;
    const int end   = base + v;          // inclusive cumsum
    const int start = end - d;
    const int len   = s_len;

    if (tid == 0) g_len[b] = len;

    // mask for this batch (coalesced; T/S = 2 iterations)
    for (int p = tid; p < T; p += S)
        mask[b * T + p] = (p >= len) ? 1.0f : 0.0f;

    // inverse-map scatter: slots [start, min(end, T)) get source index tid
    int* __restrict__ idx = g_idx + b * T;
    const int stop = min(end, T);
    for (int p = start; p < stop; ++p) idx[p] = tid;
    // Slots in [len, T) are never read (gather zero-fills them).

    __threadfence();
    cudaTriggerProgrammaticLaunchCompletion();
}

// ---------------------------------------------------------------------------
// Kernel 2: persistent gather. Exactly GRID_GATHER blocks (one wave, all
// resident); each grid-strides over row-chunks of RPB=16 rows. Per chunk the
// body is the proven R8 copy: 128-lane group per 8 rows, 8 independent
// float4 loads (MLP=8) then 8 streaming stores.
// ---------------------------------------------------------------------------
__global__ void __launch_bounds__(256, 8)
gather_kernel(const float* __restrict__ x,
              float* __restrict__ out,
              int S, int T, int D, int nchunks) {
    const int lane    = threadIdx.x & 127;
    const int grp     = threadIdx.x >> 7;          // 0 or 1
    const int strideV = D >> 2;                    // float4s per row (=128)
    const int cpb     = T / RPB;                   // chunks per batch (=128)

    // Wait until the prep grid has triggered completion (HW grid dependency).
    cudaGridDependencySynchronize();

    for (int chunk = blockIdx.x; chunk < nchunks; chunk += GRID_GATHER) {
        const int b    = chunk / cpb;
        const int row0 = chunk * RPB + grp * ROWS;     // global (b,t) row
        const int t0   = row0 - b * T;
        const int len  = g_len[b];                     // L1-resident broadcast

        // source indices: 32B broadcast (masked slots' values unused; any
        // stale value there is a prior index in [0, S), in-bounds)
        const int4* __restrict__ ip =
            reinterpret_cast<const int4*>(g_idx + row0);
        const int4 i0 = __ldg(ip);
        const int4 i1 = __ldg(ip + 1);
        const int idx[ROWS] = {i0.x, i0.y, i0.z, i0.w, i1.x, i1.y, i1.z, i1.w};

        const float4* __restrict__ xv =
            reinterpret_cast<const float4*>(x + (size_t)b * S * D) + lane;
        float4* __restrict__ dst =
            reinterpret_cast<float4*>(out + (size_t)row0 * D) + lane;

        float4 v[ROWS];
        #pragma unroll
        for (int r = 0; r < ROWS; ++r) {
            if (t0 + r < len)
                v[r] = xv[(size_t)idx[r] * strideV];
            else
                v[r] = make_float4(0.f, 0.f, 0.f, 0.f);
        }
        #pragma unroll
        for (int r = 0; r < ROWS; ++r)
            __stcs(dst + (size_t)r * strideV, v[r]);
    }
}

// ---------------------------------------------------------------------------
extern "C" void kernel_launch(void* const* d_in, const int* in_sizes, int n_in,
                              void* d_out, int out_size) {
    const float* x   = (const float*)d_in[0];
    const int*   dur = (const int*)d_in[1];

    const int BS = in_sizes[1];               // B*S = 65536
    const int B  = BATCH;                     // 64
    const int S  = BS / B;                    // 1024
    const int D  = in_sizes[0] / BS;          // 512
    const int T  = out_size / (B * (D + 1));  // 2048

    float* out  = (float*)d_out;
    float* mask = out + (size_t)B * T * D;
    const int nchunks = B * T / RPB;          // 8192

    prep_kernel<<<B, S>>>(dur, mask, S, T);

    // Persistent gather with programmatic dependent launch.
    cudaLaunchConfig_t cfg = {};
    cfg.gridDim  = dim3(GRID_GATHER, 1, 1);
    cfg.blockDim = dim3(256, 1, 1);
    cfg.dynamicSmemBytes = 0;
    cfg.stream = 0;
    cudaLaunchAttribute attr[1];
    attr[0].id = cudaLaunchAttributeProgrammaticStreamSerialization;
    attr[0].val.programmaticStreamSerializationAllowed = 1;
    cfg.attrs = attr;
    cfg.numAttrs = 1;
    cudaLaunchKernelEx(&cfg, gather_kernel, x, out, S, T, D, nchunks);
}

// round 12
// speedup vs baseline: 1.1755x; 1.1755x over previous
#include <cuda_runtime.h>
#include <cstdint>

// Shape (from reference setup_inputs): B=64, S=1024, D=512, T=2048.
// S, D, T re-derived from in_sizes/out_size at launch; B fixed.
#define BATCH 64
#define MAX_S 1024
#define ROWS  8        // output rows per 128-lane group
#define RPB   16       // rows per 256-thread block (2 groups)

// ---------------------------------------------------------------------------
// Single fused kernel, one block per 16 consecutive output rows of a batch.
// Each block independently:
//   1) loads the batch's S=1024 durations (int4/thread; L2-resident, shared
//      by the 128 blocks of the batch),
//   2) warp-shuffle scans them into an inclusive cum[] in shared memory,
//   3) 16 lanes binary-search cum for their row's source index + write mask,
//   4) 2 groups of 128 lanes copy 8 rows each: 8 independent float4 loads
//      (MLP=8) then 8 streaming stores.
// No inter-block communication of any kind.
// ---------------------------------------------------------------------------
__global__ void __launch_bounds__(256, 8)
lenreg_kernel(const float* __restrict__ x,
              const int*   __restrict__ dur,
              float* __restrict__ out,
              float* __restrict__ mask,
              int S, int T, int D)
{
    __shared__ int cum[MAX_S];
    __shared__ int wsum[8];
    __shared__ int idx_sh[RPB];

    const int cpb = T / RPB;                     // chunks per batch (=128)
    const int b   = blockIdx.x / cpb;
    const int t0c = (blockIdx.x - b * cpb) * RPB;   // first row (in-batch)
    const int tid = threadIdx.x;
    const int ln  = tid & 31;
    const int wid = tid >> 5;

    // ---- 1) load 4 durations per thread -----------------------------------
    const int4 d4 = *reinterpret_cast<const int4*>(dur + b * S + tid * 4);
    const int s = d4.x + d4.y + d4.z + d4.w;

    // ---- 2) block-wide inclusive scan -------------------------------------
    int v = s;                                   // intra-warp inclusive scan
    #pragma unroll
    for (int o = 1; o < 32; o <<= 1) {
        int n = __shfl_up_sync(0xffffffffu, v, o);
        if (ln >= o) v += n;
    }
    if (ln == 31) wsum[wid] = v;
    __syncthreads();
    if (tid < 8) {                               // scan the 8 warp totals
        int w = wsum[tid];
        #pragma unroll
        for (int o = 1; o < 8; o <<= 1) {
            int n = __shfl_up_sync(0xffu, w, o);
            if (tid >= o) w += n;
        }
        wsum[tid] = w;
    }
    __syncthreads();

    const int base = (wid ? wsum[wid - 1] : 0) + (v - s);  // exclusive prefix
    const int len  = wsum[7];

    int4 c;                                      // inclusive cum of 4 elems
    c.x = base + d4.x;
    c.y = c.x + d4.y;
    c.z = c.y + d4.z;
    c.w = c.z + d4.w;
    *reinterpret_cast<int4*>(cum + tid * 4) = c; // STS.128, conflict-free
    __syncthreads();

    // ---- 3) 16 parallel binary searches + mask ----------------------------
    if (tid < RPB) {
        const int t = t0c + tid;
        // searchsorted(cum, t, side='right'): count of cum[j] <= t
        int lo = 0, hi = S;
        while (lo < hi) {
            const int mid  = (lo + hi) >> 1;
            const bool le  = (cum[mid] <= t);
            lo = le ? mid + 1 : lo;
            hi = le ? hi : mid;
        }
        idx_sh[tid] = min(lo, S - 1);
        mask[b * T + t] = (t >= len) ? 1.0f : 0.0f;
    }
    __syncthreads();

    // ---- 4) copy: 2 groups x 8 rows ---------------------------------------
    const int lane = tid & 127;
    const int grp  = tid >> 7;                   // 0 or 1
    const int t0   = t0c + grp * ROWS;
    const int row0 = b * T + t0;                 // global output row

    int idx[ROWS];
    #pragma unroll
    for (int r = 0; r < ROWS; ++r)
        idx[r] = idx_sh[grp * ROWS + r];         // LDS broadcast

    const float4* __restrict__ xv =
        reinterpret_cast<const float4*>(x + (size_t)b * S * D) + lane;
    float4* __restrict__ dst =
        reinterpret_cast<float4*>(out + (size_t)row0 * D) + lane;
    const int strideV = D >> 2;                  // float4s per row (=128)

    float4 vv[ROWS];                             // 8 independent loads (MLP=8)
    #pragma unroll
    for (int r = 0; r < ROWS; ++r) {
        if (t0 + r < len)
            vv[r] = xv[(size_t)idx[r] * strideV];
        else
            vv[r] = make_float4(0.f, 0.f, 0.f, 0.f);
    }
    #pragma unroll
    for (int r = 0; r < ROWS; ++r)
        __stcs(dst + (size_t)r * strideV, vv[r]);
}

// ---------------------------------------------------------------------------
extern "C" void kernel_launch(void* const* d_in, const int* in_sizes, int n_in,
                              void* d_out, int out_size) {
    const float* x   = (const float*)d_in[0];
    const int*   dur = (const int*)d_in[1];

    const int BS = in_sizes[1];               // B*S = 65536
    const int B  = BATCH;                     // 64
    const int S  = BS / B;                    // 1024
    const int D  = in_sizes[0] / BS;          // 512
    const int T  = out_size / (B * (D + 1));  // 2048

    float* out  = (float*)d_out;
    float* mask = out + (size_t)B * T * D;

    lenreg_kernel<<<(B * T) / RPB, 256>>>(x, dur, out, mask, S, T, D);
}